// round 7
// baseline (speedup 1.0000x reference)
#include <cuda_runtime.h>
#include <cuda_bf16.h>
#include <math.h>
#include <stdint.h>

#define BATCH 8
#define CDIM  128
#define HW    128
#define LPIX  16384          // 128*128
#define NPIX  131072         // BATCH*LPIX
#define NH    16
#define QM    512
#define HIDN  340
#define HID2N 680
#define NSPLIT 16
#define ATT_SCALE 0.35355339059327373f  // 8^-0.5

typedef __nv_bfloat16 bf16;

// ---------------- scratch (static device globals; no runtime alloc) ----------------
static __device__ float g_qkvo[(size_t)BATCH*QM*LPIX];     // 268MB fp32
static __device__ float g_po  [(size_t)BATCH*CDIM*LPIX];   // 67MB
static __device__ float g_xb  [(size_t)BATCH*CDIM*LPIX];   // 67MB
static __device__ float g_p   [(size_t)BATCH*HID2N*LPIX];  // 356MB fp32 (precision)
static __device__ bf16  g_gt  [(size_t)BATCH*HIDN*LPIX];   // 89MB bf16
static __device__ float g_part[BATCH*NH*NSPLIT*80];
static __device__ float g_kv[BATCH*NH*64];
static __device__ float g_mk[BATCH*NH*8];
static __device__ float g_mv[BATCH*NH*8];
static __device__ float g_w1p[QM*CDIM];
static __device__ float g_rs1[QM];
static __device__ float g_c1[QM];
static __device__ float g_w2p[HID2N*CDIM];
static __device__ float g_rs2[HID2N];
static __device__ float g_c2[HID2N];
static __device__ float g_wproj[CDIM*CDIM];
static __device__ float g_wffo[CDIM*HIDN];

// ---------------- tf32 helpers ----------------
__device__ __forceinline__ unsigned f2tf(float f){
  unsigned u; asm("cvt.rna.tf32.f32 %0, %1;" : "=r"(u) : "f"(f)); return u;
}
__device__ __forceinline__ void mma8(float* c, const unsigned* a, const unsigned* b){
  asm volatile("mma.sync.aligned.m16n8k8.row.col.f32.tf32.tf32.f32 "
    "{%0,%1,%2,%3}, {%4,%5,%6,%7}, {%8,%9}, {%0,%1,%2,%3};"
    : "+f"(c[0]), "+f"(c[1]), "+f"(c[2]), "+f"(c[3])
    : "r"(a[0]), "r"(a[1]), "r"(a[2]), "r"(a[3]), "r"(b[0]), "r"(b[1]));
}

template<typename TC>
__device__ __forceinline__ void st2(TC* C, size_t ci, float v0, float v1);
template<> __device__ __forceinline__ void st2<float>(float* C, size_t ci, float v0, float v1){
  float2 o; o.x = v0; o.y = v1; *(float2*)&C[ci] = o;
}
template<> __device__ __forceinline__ void st2<bf16>(bf16* C, size_t ci, float v0, float v1){
  __nv_bfloat162 o; o.x = __float2bfloat16(v0); o.y = __float2bfloat16(v1);
  *(__nv_bfloat162*)&C[ci] = o;
}

// ---------------- fold LN affine into conv1x1 weights (tf32 pre-rounded) ----------------
__global__ void fold_k(const float* __restrict__ w, const float* __restrict__ lnw,
                       const float* __restrict__ lnb, const float* __restrict__ bias,
                       float* __restrict__ wp, float* __restrict__ rs,
                       float* __restrict__ cst, int hasBias){
  int o = blockIdx.x, c = threadIdx.x;
  float wv = w[o*CDIM + c];
  float wl = __uint_as_float(f2tf(wv * lnw[c]));   // round to tf32 ONCE
  wp[o*CDIM + c] = wl;
  float cb = wv * lnb[c];
  __shared__ float sa[CDIM], sb[CDIM];
  sa[c] = wl; sb[c] = cb;
  __syncthreads();
  for (int st = 64; st > 0; st >>= 1){
    if (c < st){ sa[c] += sa[c+st]; sb[c] += sb[c+st]; }
    __syncthreads();
  }
  if (c == 0){ rs[o] = sa[0]; cst[o] = sb[0] + (hasBias ? bias[o] : 0.f); }
}

// ---------------- pre-round plain weights to tf32 ----------------
__global__ void roundw_k(const float* __restrict__ w, float* __restrict__ o, int n){
  int i = blockIdx.x*256 + threadIdx.x;
  if (i < n) o[i] = __uint_as_float(f2tf(w[i]));
}

// ======== pipelined TF32 GEMM, cp.async 2-stage, 128x128 tile ========
// A must be PRE-ROUNDED to tf32 (raw-bit fragments, no cvt).
// C[b,m,l] = sum_k A[m,k]*B[b,k,l] + epilogue
// Block tile 128(M) x 128(N), BK=32, 8 warps 2x4, warp tile 64x32.
// STATS=1 (with EPI 0): LN stats computed in-kernel from the streamed B tile
//   (requires K == CDIM == full channel dim).
// EPI 0: LN-fold   v = r[col]*acc - m[col]*rowS[row] + rowC[row]
// EPI 1: bias+res  v = acc + rowC[row] + res[idx]
#define GEMM_SMEM2 ((2*128*36 + 2*32*136 + 2*8*128)*4)
template<int EPI, int STATS, typename TC>
__global__ __launch_bounds__(256)
void gemm128(const float* __restrict__ A, const float* __restrict__ Bm,
             TC* __restrict__ C, int M, int K,
             const float* __restrict__ rowS, const float* __restrict__ rowC,
             const float* __restrict__ res){
  extern __shared__ float smem[];
  unsigned (*As)[128][36] = (unsigned(*)[128][36])smem;
  float    (*Bs)[32][136] = (float(*)[32][136])(smem + 2*128*36);
  float* s_sum = smem + 2*128*36 + 2*32*136;   // [8][128]
  float* s_sq  = s_sum + 8*128;                // [8][128]
  int tid = threadIdx.x;
  int b = blockIdx.z;
  int row0 = blockIdx.x*128;           // M fastest => B col-tile L2 reuse
  int col0 = blockIdx.y*128;
  const float* Bp = Bm + (size_t)b*K*LPIX;
  int lane = tid&31, warp = tid>>5;
  int wm = warp>>2, wn = warp&3;
  int nT = (K+31)>>5;
  unsigned sA = (unsigned)__cvta_generic_to_shared(&As[0][0][0]);
  unsigned sB = (unsigned)__cvta_generic_to_shared(&Bs[0][0][0]);

  auto issue = [&](int t){
    int s = t&1, k0 = t*32;
    #pragma unroll
    for (int i = 0; i < 4; i++){
      int id = tid + i*256;
      int m = id>>3, c4 = (id&7)*4;
      int row = row0+m, kg = k0+c4;
      const float* src = &A[(size_t)row*K + kg];
      int sz = (row < M && kg+4 <= K) ? 16 : 0;
      if (!sz) src = A;
      unsigned dst = sA + (unsigned)(((s*128 + m)*36 + c4) << 2);
      asm volatile("cp.async.ca.shared.global [%0], [%1], 16, %2;\n"
                   :: "r"(dst), "l"(src), "r"(sz));
    }
    #pragma unroll
    for (int i = 0; i < 4; i++){
      int id = tid + i*256;
      int kk = id>>5, c4 = (id&31)*4;
      int kg = k0+kk;
      const float* src = &Bp[(size_t)kg*LPIX + col0 + c4];
      int sz = (kg < K) ? 16 : 0;
      if (!sz) src = Bp;
      unsigned dst = sB + (unsigned)(((s*32 + kk)*136 + c4) << 2);
      asm volatile("cp.async.cg.shared.global [%0], [%1], 16, %2;\n"
                   :: "r"(dst), "l"(src), "r"(sz));
    }
    asm volatile("cp.async.commit_group;\n");
  };

  // stats accumulators: thread (rg = tid>>5, cq = tid&31) owns rows
  // [rg*4..rg*4+3] of each tile for cols [cq*4..cq*4+3]
  float ssum[4] = {}, ssq[4] = {};
  int rg = tid>>5, cq = tid&31;

  float acc[4][4][4] = {};
  issue(0);
  for (int t = 0; t < nT; t++){
    if (t+1 < nT){ issue(t+1); asm volatile("cp.async.wait_group 1;\n" ::: "memory"); }
    else         {             asm volatile("cp.async.wait_group 0;\n" ::: "memory"); }
    __syncthreads();
    int s = t&1;
    if (STATS){
      #pragma unroll
      for (int j = 0; j < 4; j++){
        float4 v = *(const float4*)&Bs[s][rg*4 + j][cq*4];
        ssum[0] += v.x; ssq[0] = fmaf(v.x, v.x, ssq[0]);
        ssum[1] += v.y; ssq[1] = fmaf(v.y, v.y, ssq[1]);
        ssum[2] += v.z; ssq[2] = fmaf(v.z, v.z, ssq[2]);
        ssum[3] += v.w; ssq[3] = fmaf(v.w, v.w, ssq[3]);
      }
    }
    #pragma unroll
    for (int ks = 0; ks < 4; ks++){
      int kb = ks*8;
      unsigned af[4][4], bfr[4][2];
      #pragma unroll
      for (int mt = 0; mt < 4; mt++){
        int r = wm*64 + mt*16 + (lane>>2);
        af[mt][0] = As[s][r  ][kb + (lane&3)];
        af[mt][1] = As[s][r+8][kb + (lane&3)];
        af[mt][2] = As[s][r  ][kb + 4 + (lane&3)];
        af[mt][3] = As[s][r+8][kb + 4 + (lane&3)];
      }
      #pragma unroll
      for (int nt = 0; nt < 4; nt++){
        int n = wn*32 + nt*8 + (lane>>2);
        bfr[nt][0] = f2tf(Bs[s][kb + (lane&3)][n]);
        bfr[nt][1] = f2tf(Bs[s][kb + 4 + (lane&3)][n]);
      }
      #pragma unroll
      for (int mt = 0; mt < 4; mt++)
        #pragma unroll
        for (int nt = 0; nt < 4; nt++)
          mma8(acc[mt][nt], af[mt], bfr[nt]);
    }
    __syncthreads();
  }

  if (STATS){
    #pragma unroll
    for (int j = 0; j < 4; j++){
      s_sum[rg*128 + cq*4 + j] = ssum[j];
      s_sq [rg*128 + cq*4 + j] = ssq[j];
    }
    __syncthreads();
    if (tid < 128){
      float s = 0.f, q = 0.f;
      #pragma unroll
      for (int g = 0; g < 8; g++){ s += s_sum[g*128 + tid]; q += s_sq[g*128 + tid]; }
      float mu  = s * (1.f/CDIM);
      float var = fmaxf(q*(1.f/CDIM) - mu*mu, 0.f);
      float r   = rsqrtf(var + 1e-5f);
      s_sum[tid] = r;          // rstd
      s_sq[tid]  = mu * r;     // mu*rstd
    }
    __syncthreads();
  }

  size_t cb = (size_t)b*M*LPIX;
  #pragma unroll
  for (int mt = 0; mt < 4; mt++){
    int r = row0 + wm*64 + mt*16 + (lane>>2);
    #pragma unroll
    for (int nt = 0; nt < 4; nt++){
      int lc = wn*32 + nt*8 + 2*(lane&3);
      int col = col0 + lc;
      float c0 = acc[mt][nt][0], c1 = acc[mt][nt][1];
      float c2 = acc[mt][nt][2], c3 = acc[mt][nt][3];
      if (EPI == 0){
        float r0v = s_sum[lc],  r1v = s_sum[lc+1];
        float m0v = s_sq[lc],   m1v = s_sq[lc+1];
        if (r < M)
          st2<TC>(C, cb + (size_t)r*LPIX + col,
                  r0v*c0 - m0v*rowS[r] + rowC[r],
                  r1v*c1 - m1v*rowS[r] + rowC[r]);
        if (r+8 < M)
          st2<TC>(C, cb + (size_t)(r+8)*LPIX + col,
                  r0v*c2 - m0v*rowS[r+8] + rowC[r+8],
                  r1v*c3 - m1v*rowS[r+8] + rowC[r+8]);
      } else {
        if (r < M){
          size_t ci = cb + (size_t)r*LPIX + col;
          float2 rr = *(const float2*)&res[ci];
          st2<TC>(C, ci, c0 + rowC[r] + rr.x, c1 + rowC[r] + rr.y);
        }
        if (r+8 < M){
          size_t ci = cb + (size_t)(r+8)*LPIX + col;
          float2 rr = *(const float2*)&res[ci];
          st2<TC>(C, ci, c2 + rowC[r+8] + rr.x, c3 + rowC[r+8] + rr.y);
        }
      }
    }
  }
}

// ======== TF32 GEMM with bf16 B (ffn_out), single-buffer, res epilogue ========
// A must be PRE-ROUNDED to tf32.
__global__ __launch_bounds__(256)
void gemm_bf(const float* __restrict__ A, const bf16* __restrict__ Bm,
             float* __restrict__ C, int M, int K,
             const float* __restrict__ res){
  __shared__ unsigned As[64][36];
  __shared__ unsigned Bs[32][136];
  int tid = threadIdx.x;
  int b = blockIdx.z;
  int row0 = blockIdx.x*64, col0 = blockIdx.y*128;
  const bf16* Bp = Bm + (size_t)b*K*LPIX;
  int lane = tid&31, warp = tid>>5;
  int wm = warp>>2, wn = warp&3;
  float acc[2][4][4] = {};
  int nT = (K+31)>>5;
  for (int kt = 0; kt < nT; kt++){
    int k0 = kt*32;
    #pragma unroll
    for (int i = 0; i < 2; i++){
      int id = tid + i*256;
      int m = id>>3, c4 = (id&7)*4;
      int row = row0+m, kg = k0+c4;
      float4 v = (row < M && kg+4 <= K) ? *(const float4*)&A[(size_t)row*K + kg]
                                        : make_float4(0.f,0.f,0.f,0.f);
      As[m][c4+0]=__float_as_uint(v.x); As[m][c4+1]=__float_as_uint(v.y);
      As[m][c4+2]=__float_as_uint(v.z); As[m][c4+3]=__float_as_uint(v.w);
    }
    #pragma unroll
    for (int i = 0; i < 2; i++){
      int id = tid + i*256;
      int kk = id>>4, c8 = (id&15)*8;
      int kg = k0+kk;
      uint4 v = (kg < K) ? *(const uint4*)&Bp[(size_t)kg*LPIX + col0 + c8]
                         : make_uint4(0u,0u,0u,0u);
      unsigned* d = &Bs[kk][c8];
      d[0] = (v.x & 0xffffu) << 16; d[1] = v.x & 0xffff0000u;
      d[2] = (v.y & 0xffffu) << 16; d[3] = v.y & 0xffff0000u;
      d[4] = (v.z & 0xffffu) << 16; d[5] = v.z & 0xffff0000u;
      d[6] = (v.w & 0xffffu) << 16; d[7] = v.w & 0xffff0000u;
    }
    __syncthreads();
    #pragma unroll
    for (int ks = 0; ks < 4; ks++){
      int kb = ks*8;
      unsigned af[2][4], bfr[4][2];
      #pragma unroll
      for (int mt = 0; mt < 2; mt++){
        int r = wm*32 + mt*16 + (lane>>2);
        af[mt][0] = As[r  ][kb + (lane&3)];
        af[mt][1] = As[r+8][kb + (lane&3)];
        af[mt][2] = As[r  ][kb + 4 + (lane&3)];
        af[mt][3] = As[r+8][kb + 4 + (lane&3)];
      }
      #pragma unroll
      for (int nt = 0; nt < 4; nt++){
        int n = wn*32 + nt*8 + (lane>>2);
        bfr[nt][0] = Bs[kb + (lane&3)][n];
        bfr[nt][1] = Bs[kb + 4 + (lane&3)][n];
      }
      #pragma unroll
      for (int mt = 0; mt < 2; mt++)
        #pragma unroll
        for (int nt = 0; nt < 4; nt++)
          mma8(acc[mt][nt], af[mt], bfr[nt]);
    }
    __syncthreads();
  }
  size_t cb = (size_t)b*M*LPIX;
  #pragma unroll
  for (int mt = 0; mt < 2; mt++){
    int r = row0 + wm*32 + mt*16 + (lane>>2);
    #pragma unroll
    for (int nt = 0; nt < 4; nt++){
      int col = col0 + wn*32 + nt*8 + 2*(lane&3);
      if (r < M){
        size_t ci = cb + (size_t)r*LPIX + col;
        float2 rr = *(const float2*)&res[ci];
        st2<float>(C, ci, acc[mt][nt][0] + rr.x, acc[mt][nt][1] + rr.y);
      }
      if (r+8 < M){
        size_t ci = cb + (size_t)(r+8)*LPIX + col;
        float2 rr = *(const float2*)&res[ci];
        st2<float>(C, ci, acc[mt][nt][2] + rr.x, acc[mt][nt][3] + rr.y);
      }
    }
  }
}

// ---------------- RoPE helpers (head_dim = 8) ----------------
__device__ __forceinline__ void rope_sc8(int l, float* sn, float* cs){
  int hh = l >> 7, ww = l & 127;
  sincosf((float)hh,          &sn[0], &cs[0]);
  sincosf((float)hh * 1e-4f,  &sn[1], &cs[1]);
  sincosf((float)ww,          &sn[2], &cs[2]);
  sincosf((float)ww * 1e-4f,  &sn[3], &cs[3]);
}
__device__ __forceinline__ void theta_shift8(const float* x, const float* sn,
                                             const float* cs, float* y){
  #pragma unroll
  for (int p = 0; p < 4; p++){
    y[2*p]   = x[2*p]  *cs[p] - x[2*p+1]*sn[p];
    y[2*p+1] = x[2*p+1]*cs[p] + x[2*p]  *sn[p];
  }
}

// ---------------- attention reductions: split-K partials ----------------
__global__ __launch_bounds__(256)
void attn_reduce_k(){
  int nh = blockIdx.x, b = blockIdx.y, sp = blockIdx.z;
  const float* kp = g_qkvo + ((size_t)b*QM +   CDIM + nh*8)*LPIX;
  const float* vp = g_qkvo + ((size_t)b*QM + 2*CDIM + nh*8)*LPIX;
  float mk[8] = {}, mv[8] = {}, kv[64] = {};
  int l0 = sp*(LPIX/NSPLIT), l1 = l0 + (LPIX/NSPLIT);
  for (int l = l0 + threadIdx.x; l < l1; l += 256){
    float kk[8], vv[8], ks[8], sn[4], cs[4];
    #pragma unroll
    for (int d = 0; d < 8; d++){
      float kl = kp[(size_t)d*LPIX + l];
      kk[d] = kl > 0.f ? kl + 1.f : expf(kl);   // elu(k)+1
      vv[d] = vp[(size_t)d*LPIX + l];
      mk[d] += kk[d];
      mv[d] += vv[d];
    }
    rope_sc8(l, sn, cs);
    theta_shift8(kk, sn, cs, ks);
    #pragma unroll
    for (int d = 0; d < 8; d++)
      #pragma unroll
      for (int e = 0; e < 8; e++)
        kv[d*8+e] = fmaf(ks[d], vv[e], kv[d*8+e]);
  }
  __shared__ float red[8][80];
  int warp = threadIdx.x >> 5, lane = threadIdx.x & 31;
  #pragma unroll
  for (int i = 0; i < 8; i++){
    #pragma unroll
    for (int off = 16; off > 0; off >>= 1){
      mk[i] += __shfl_down_sync(0xffffffffu, mk[i], off);
      mv[i] += __shfl_down_sync(0xffffffffu, mv[i], off);
    }
  }
  #pragma unroll
  for (int i = 0; i < 64; i++)
    #pragma unroll
    for (int off = 16; off > 0; off >>= 1)
      kv[i] += __shfl_down_sync(0xffffffffu, kv[i], off);
  if (lane == 0){
    #pragma unroll
    for (int i = 0; i < 8; i++){ red[warp][i] = mk[i]; red[warp][8+i] = mv[i]; }
    #pragma unroll
    for (int i = 0; i < 64; i++) red[warp][16+i] = kv[i];
  }
  __syncthreads();
  int t = threadIdx.x;
  if (t < 80){
    float s = 0.f;
    #pragma unroll
    for (int w = 0; w < 8; w++) s += red[w][t];
    g_part[((b*NH + nh)*NSPLIT + sp)*80 + t] = s;
  }
}

// ---------------- finalize: sum split partials (deterministic) ----------------
__global__ void attn_fin_k(){
  int o = blockIdx.x;            // b*NH + nh
  int t = threadIdx.x;           // 0..79
  float s = 0.f;
  #pragma unroll
  for (int sp = 0; sp < NSPLIT; sp++) s += g_part[(o*NSPLIT + sp)*80 + t];
  if (t < 8)        g_mk[o*8 + t]       = s * (1.f/LPIX);
  else if (t < 16)  g_mv[o*8 + t - 8]   = s * (1.f/LPIX);
  else              g_kv[o*64 + t - 16] = s * (ATT_SCALE/LPIX);
}

// ---------------- fused: lepe 5x5 dwconv + attention apply + gate by o ----------------
// grid (4, 4, BATCH*NH); block 256 = 32x8, each thread 4 rows
__global__ __launch_bounds__(256)
void attn_apply_k(const float* __restrict__ lw, const float* __restrict__ lb){
  int z = blockIdx.z;
  int b = z >> 4, nh = z & 15;
  __shared__ float sv[8][36][36];
  __shared__ float swk[8][25], sb8[8];
  __shared__ float skv[64], smk[8], smv[8];
  int tid = threadIdx.x;
  int o = b*NH + nh;
  if (tid < 64)       skv[tid]      = g_kv[o*64 + tid];
  else if (tid < 72)  smk[tid-64]   = g_mk[o*8 + tid-64];
  else if (tid < 80)  smv[tid-72]   = g_mv[o*8 + tid-72];
  else if (tid < 88)  sb8[tid-80]   = lb[nh*8 + tid-80];
  if (tid < 200)      swk[tid/25][tid%25] = lw[(nh*8 + tid/25)*25 + tid%25];

  // load v halo tile (8 channels, 36x36)
  const float* vbase = g_qkvo + ((size_t)b*QM + 2*CDIM + nh*8)*LPIX;
  int y0 = blockIdx.y*32 - 2, x0 = blockIdx.x*32 - 2;
  for (int i = tid; i < 8*36*36; i += 256){
    int e = i / 1296, r = i - e*1296;
    int yy = r/36, xx = r - yy*36;
    int gy = y0 + yy, gx = x0 + xx;
    sv[e][yy][xx] = ((unsigned)gy < 128u && (unsigned)gx < 128u)
                    ? vbase[(size_t)e*LPIX + gy*HW + gx] : 0.f;
  }
  __syncthreads();

  int tx = tid & 31, tyb = tid >> 5;
  int px0 = blockIdx.x*32, py0 = blockIdx.y*32;
  const float* qbase = g_qkvo + ((size_t)b*QM +          nh*8)*LPIX;
  const float* obase = g_qkvo + ((size_t)b*QM + 3*CDIM + nh*8)*LPIX;
  float*       pbase = g_po   + ((size_t)b*CDIM + nh*8)*LPIX;
  #pragma unroll
  for (int rr = 0; rr < 4; rr++){
    int ty = tyb + rr*8;
    int l = (py0 + ty)*HW + px0 + tx;
    float qq[8], qs[8], sn[4], cs[4];
    #pragma unroll
    for (int d = 0; d < 8; d++){
      float qv = qbase[(size_t)d*LPIX + l];
      qq[d] = qv > 0.f ? qv + 1.f : expf(qv);     // elu(q)+1
    }
    float zq = 0.f;
    #pragma unroll
    for (int d = 0; d < 8; d++) zq = fmaf(qq[d], smk[d], zq);
    zq *= ATT_SCALE;
    rope_sc8(l, sn, cs);
    theta_shift8(qq, sn, cs, qs);
    float f = 1.f + 1.f/(zq + 1e-6f);
    #pragma unroll
    for (int e = 0; e < 8; e++){
      // lepe for this pixel/channel from smem halo tile
      float lep = sb8[e];
      #pragma unroll
      for (int dy = 0; dy < 5; dy++)
        #pragma unroll
        for (int dx = 0; dx < 5; dx++)
          lep = fmaf(sv[e][ty+dy][tx+dx], swk[e][dy*5+dx], lep);
      float r = 0.f;
      #pragma unroll
      for (int d = 0; d < 8; d++) r = fmaf(qs[d], skv[d*8 + e], r);
      float rv = r*f - zq*smv[e];
      pbase[(size_t)e*LPIX + l] = (rv + lep) * obase[(size_t)e*LPIX + l];
    }
  }
}

// ---------------- FFN: 3x3 depthwise on both halves + gelu(x1)*x2 ----------------
__global__ __launch_bounds__(256)
void ffn_dw_k(const float* __restrict__ w){
  int z = blockIdx.z;
  int b = z / HIDN, j = z - b*HIDN;
  const float* s1 = g_p + ((size_t)b*HID2N + j)*LPIX;
  const float* s2 = g_p + ((size_t)b*HID2N + HIDN + j)*LPIX;
  __shared__ float t1[34][34], t2[34][34];
  __shared__ float w1[9], w2[9];
  int tid = threadIdx.x;
  if (tid < 9)        w1[tid]   = w[j*9 + tid];
  else if (tid < 18)  w2[tid-9] = w[(HIDN + j)*9 + tid - 9];
  int y0 = blockIdx.y*32 - 1, x0 = blockIdx.x*32 - 1;
  for (int i = tid; i < 34*34; i += 256){
    int yy = i/34, xx = i - yy*34;
    int gy = y0 + yy, gx = x0 + xx;
    bool in = ((unsigned)gy < 128u && (unsigned)gx < 128u);
    t1[yy][xx] = in ? s1[gy*HW + gx] : 0.f;
    t2[yy][xx] = in ? s2[gy*HW + gx] : 0.f;
  }
  __syncthreads();
  int tx = tid & 31, tyb = tid >> 5;
  bf16* dst = g_gt + ((size_t)b*HIDN + j)*LPIX;
  #pragma unroll
  for (int r = 0; r < 4; r++){
    int ty = tyb + r*8;
    float a1 = 0.f, a2 = 0.f;
    #pragma unroll
    for (int dy = 0; dy < 3; dy++)
      #pragma unroll
      for (int dx = 0; dx < 3; dx++){
        a1 = fmaf(t1[ty+dy][tx+dx], w1[dy*3+dx], a1);
        a2 = fmaf(t2[ty+dy][tx+dx], w2[dy*3+dx], a2);
      }
    float ge = a1 * normcdff(a1);                 // exact gelu
    dst[(blockIdx.y*32 + ty)*HW + blockIdx.x*32 + tx] = __float2bfloat16(ge * a2);
  }
}

// ---------------- launch ----------------
extern "C" void kernel_launch(void* const* d_in, const int* in_sizes, int n_in,
                              void* d_out, int out_size){
  (void)in_sizes; (void)n_in; (void)out_size;
  const float* x        = (const float*)d_in[0];
  const float* ln1_w    = (const float*)d_in[1];
  const float* ln1_b    = (const float*)d_in[2];
  const float* qkvo_w   = (const float*)d_in[3];
  const float* qkvo_b   = (const float*)d_in[4];
  const float* lepe_w   = (const float*)d_in[5];
  const float* lepe_b   = (const float*)d_in[6];
  const float* proj_w   = (const float*)d_in[7];
  const float* proj_b   = (const float*)d_in[8];
  const float* ln2_w    = (const float*)d_in[9];
  const float* ln2_b    = (const float*)d_in[10];
  const float* ffn_in_w = (const float*)d_in[11];
  const float* ffn_dw_w = (const float*)d_in[12];
  const float* ffn_out_w= (const float*)d_in[13];
  float* out = (float*)d_out;

  void *p_qkvo, *p_po, *p_xb, *p_p, *p_gt;
  void *p_w1p, *p_rs1, *p_c1, *p_w2p, *p_rs2, *p_c2, *p_wproj, *p_wffo;
  cudaGetSymbolAddress(&p_qkvo,  g_qkvo);
  cudaGetSymbolAddress(&p_po,    g_po);
  cudaGetSymbolAddress(&p_xb,    g_xb);
  cudaGetSymbolAddress(&p_p,     g_p);
  cudaGetSymbolAddress(&p_gt,    g_gt);
  cudaGetSymbolAddress(&p_w1p,   g_w1p);
  cudaGetSymbolAddress(&p_rs1,   g_rs1);
  cudaGetSymbolAddress(&p_c1,    g_c1);
  cudaGetSymbolAddress(&p_w2p,   g_w2p);
  cudaGetSymbolAddress(&p_rs2,   g_rs2);
  cudaGetSymbolAddress(&p_c2,    g_c2);
  cudaGetSymbolAddress(&p_wproj, g_wproj);
  cudaGetSymbolAddress(&p_wffo,  g_wffo);

  static int smem_set = 0;
  if (!smem_set){
    cudaFuncSetAttribute(gemm128<0,1,float>, cudaFuncAttributeMaxDynamicSharedMemorySize, GEMM_SMEM2);
    cudaFuncSetAttribute(gemm128<1,0,float>, cudaFuncAttributeMaxDynamicSharedMemorySize, GEMM_SMEM2);
    smem_set = 1;
  }

  // fold LN affine into conv weights + pre-round to tf32 (tiny)
  fold_k<<<QM,    CDIM>>>(qkvo_w,   ln1_w, ln1_b, qkvo_b, (float*)p_w1p, (float*)p_rs1, (float*)p_c1, 1);
  fold_k<<<HID2N, CDIM>>>(ffn_in_w, ln2_w, ln2_b, nullptr,(float*)p_w2p, (float*)p_rs2, (float*)p_c2, 0);
  roundw_k<<<(CDIM*CDIM+255)/256, 256>>>(proj_w,    (float*)p_wproj, CDIM*CDIM);
  roundw_k<<<(CDIM*HIDN+255)/256, 256>>>(ffn_out_w, (float*)p_wffo,  CDIM*HIDN);

  // qkvo = conv1x1(LN1(x)) + b   (LN stats computed in-kernel)
  gemm128<0,1,float><<<dim3(4, 128, BATCH), 256, GEMM_SMEM2>>>(
      (float*)p_w1p, x, (float*)p_qkvo, QM, CDIM,
      (float*)p_rs1, (float*)p_c1, nullptr);

  // per-(b,head) reductions: meank, meanv, kv  (split-K, deterministic)
  attn_reduce_k<<<dim3(NH, BATCH, NSPLIT), 256>>>();
  attn_fin_k<<<BATCH*NH, 80>>>();

  // po = (q@kv*(1+1/z) - z*meanv + lepe5x5(v)) * o   (lepe fused)
  attn_apply_k<<<dim3(4, 4, BATCH*NH), 256>>>(lepe_w, lepe_b);

  // xb = x + conv1x1(po, proj_w) + proj_b
  gemm128<1,0,float><<<dim3(1, 128, BATCH), 256, GEMM_SMEM2>>>(
      (float*)p_wproj, (float*)p_po, (float*)p_xb, CDIM, CDIM,
      nullptr, proj_b, x);

  // p = conv1x1(LN2(xb), ffn_in_w)   (LN stats in-kernel, fp32 out)
  gemm128<0,1,float><<<dim3(6, 128, BATCH), 256, GEMM_SMEM2>>>(
      (float*)p_w2p, (float*)p_xb, (float*)p_p, HID2N, CDIM,
      (float*)p_rs2, (float*)p_c2, nullptr);

  // g = gelu(dw3(p[:340])) * dw3(p[340:])  (fp32 in, bf16 out)
  ffn_dw_k<<<dim3(4, 4, BATCH*HIDN), 256>>>(ffn_dw_w);

  // out = xb + conv1x1(g, ffn_out_w)  (bf16 B, pre-rounded A)
  gemm_bf<<<dim3(2, 128, BATCH), 256>>>((float*)p_wffo, (bf16*)p_gt, out, CDIM, HIDN,
                                        (float*)p_xb);
}

// round 9
// speedup vs baseline: 1.3440x; 1.3440x over previous
#include <cuda_runtime.h>
#include <cuda_bf16.h>
#include <math.h>
#include <stdint.h>

#define BATCH 8
#define CDIM  128
#define HW    128
#define LPIX  16384          // 128*128
#define NPIX  131072         // BATCH*LPIX
#define NH    16
#define QM    512
#define HIDN  340
#define HID2N 680
#define NSPLIT 16
#define ATT_SCALE 0.35355339059327373f  // 8^-0.5

typedef __nv_bfloat16 bf16;

// ---------------- scratch (static device globals; no runtime alloc) ----------------
static __device__ float g_rstd1[NPIX];
static __device__ float g_mur1[NPIX];
static __device__ float g_rstd2[NPIX];
static __device__ float g_mur2[NPIX];
static __device__ float g_qkvo[(size_t)BATCH*QM*LPIX];     // 268MB fp32
static __device__ float g_lepe[(size_t)BATCH*CDIM*LPIX];   // 67MB
static __device__ float g_po  [(size_t)BATCH*CDIM*LPIX];   // 67MB
static __device__ float g_xb  [(size_t)BATCH*CDIM*LPIX];   // 67MB
static __device__ float g_p   [(size_t)BATCH*HID2N*LPIX];  // 356MB fp32 (precision)
static __device__ bf16  g_gt  [(size_t)BATCH*HIDN*LPIX];   // 89MB bf16
static __device__ float g_part[BATCH*NH*NSPLIT*80];
static __device__ float g_kv[BATCH*NH*64];
static __device__ float g_mk[BATCH*NH*8];
static __device__ float g_mv[BATCH*NH*8];
static __device__ float g_w1p[QM*CDIM];
static __device__ float g_rs1[QM];
static __device__ float g_c1[QM];
static __device__ float g_w2p[HID2N*CDIM];
static __device__ float g_rs2[HID2N];
static __device__ float g_c2[HID2N];
static __device__ float g_wproj[CDIM*CDIM];
static __device__ float g_wffo[CDIM*HIDN];

// ---------------- tf32 helpers ----------------
__device__ __forceinline__ unsigned f2tf(float f){
  unsigned u; asm("cvt.rna.tf32.f32 %0, %1;" : "=r"(u) : "f"(f)); return u;
}
__device__ __forceinline__ void mma8(float* c, const unsigned* a, const unsigned* b){
  asm volatile("mma.sync.aligned.m16n8k8.row.col.f32.tf32.tf32.f32 "
    "{%0,%1,%2,%3}, {%4,%5,%6,%7}, {%8,%9}, {%0,%1,%2,%3};"
    : "+f"(c[0]), "+f"(c[1]), "+f"(c[2]), "+f"(c[3])
    : "r"(a[0]), "r"(a[1]), "r"(a[2]), "r"(a[3]), "r"(b[0]), "r"(b[1]));
}

template<typename TC>
__device__ __forceinline__ void st2(TC* C, size_t ci, float v0, float v1);
template<> __device__ __forceinline__ void st2<float>(float* C, size_t ci, float v0, float v1){
  float2 o; o.x = v0; o.y = v1; *(float2*)&C[ci] = o;
}
template<> __device__ __forceinline__ void st2<bf16>(bf16* C, size_t ci, float v0, float v1){
  __nv_bfloat162 o; o.x = __float2bfloat16(v0); o.y = __float2bfloat16(v1);
  *(__nv_bfloat162*)&C[ci] = o;
}

// ---------------- LN stats per pixel (over 128 channels) ----------------
__global__ void ln_stats_k(const float* __restrict__ x, float* __restrict__ rstd,
                           float* __restrict__ mur){
  int g = blockIdx.x*blockDim.x + threadIdx.x;
  int b = g >> 14;
  int l = g & (LPIX-1);
  const float* xp = x + (size_t)b*CDIM*LPIX + l;
  float s = 0.f, s2 = 0.f;
  #pragma unroll 16
  for (int c = 0; c < CDIM; c++){
    float v = xp[(size_t)c*LPIX];
    s += v; s2 += v*v;
  }
  float mu  = s * (1.f/CDIM);
  float var = fmaxf(s2*(1.f/CDIM) - mu*mu, 0.f);
  float r   = rsqrtf(var + 1e-5f);
  rstd[g] = r;
  mur[g]  = mu * r;
}

// ---------------- fold LN affine into conv1x1 weights (tf32 pre-rounded) ----------------
__global__ void fold_k(const float* __restrict__ w, const float* __restrict__ lnw,
                       const float* __restrict__ lnb, const float* __restrict__ bias,
                       float* __restrict__ wp, float* __restrict__ rs,
                       float* __restrict__ cst, int hasBias){
  int o = blockIdx.x, c = threadIdx.x;
  float wv = w[o*CDIM + c];
  float wl = __uint_as_float(f2tf(wv * lnw[c]));   // round to tf32 ONCE
  wp[o*CDIM + c] = wl;
  float cb = wv * lnb[c];
  __shared__ float sa[CDIM], sb[CDIM];
  sa[c] = wl; sb[c] = cb;
  __syncthreads();
  for (int st = 64; st > 0; st >>= 1){
    if (c < st){ sa[c] += sa[c+st]; sb[c] += sb[c+st]; }
    __syncthreads();
  }
  if (c == 0){ rs[o] = sa[0]; cst[o] = sb[0] + (hasBias ? bias[o] : 0.f); }
}

// ---------------- pre-round plain weights to tf32 ----------------
__global__ void roundw_k(const float* __restrict__ w, float* __restrict__ o, int n){
  int i = blockIdx.x*256 + threadIdx.x;
  if (i < n) o[i] = __uint_as_float(f2tf(w[i]));
}

// ======== pipelined TF32 GEMM (fp32 B), cp.async 2-stage, 128x128 tile ========
// A must be PRE-ROUNDED to tf32 (raw-bit fragments, no cvt).
// C[b,m,l] = sum_k A[m,k]*B[b,k,l] + epilogue
// Block tile 128(M) x 128(N), BK=32, 8 warps 2x4, warp tile 64x32.
// EPI 0: LN-fold   v = colR[g]*acc - colMR[g]*rowS[m] + rowC[m]
// EPI 1: bias+res  v = acc + rowC[m] + res[idx]
#define GEMM_SMEM2 ((2*128*36 + 2*32*136)*4)
template<int EPI, typename TC>
__global__ __launch_bounds__(256, 2)
void gemm128(const float* __restrict__ A, const float* __restrict__ Bm,
             TC* __restrict__ C, int M, int K,
             const float* __restrict__ rowS, const float* __restrict__ rowC,
             const float* __restrict__ colR, const float* __restrict__ colMR,
             const float* __restrict__ res){
  extern __shared__ float smem[];
  unsigned (*As)[128][36] = (unsigned(*)[128][36])smem;
  float    (*Bs)[32][136] = (float(*)[32][136])(smem + 2*128*36);
  int tid = threadIdx.x;
  int b = blockIdx.z;
  int row0 = blockIdx.x*128;           // M fastest => B col-tile L2 reuse
  int col0 = blockIdx.y*128;
  const float* Bp = Bm + (size_t)b*K*LPIX;
  int lane = tid&31, warp = tid>>5;
  int wm = warp>>2, wn = warp&3;
  int nT = (K+31)>>5;
  unsigned sA = (unsigned)__cvta_generic_to_shared(&As[0][0][0]);
  unsigned sB = (unsigned)__cvta_generic_to_shared(&Bs[0][0][0]);

  auto issue = [&](int t){
    int s = t&1, k0 = t*32;
    #pragma unroll
    for (int i = 0; i < 4; i++){
      int id = tid + i*256;
      int m = id>>3, c4 = (id&7)*4;
      int row = row0+m, kg = k0+c4;
      const float* src = &A[(size_t)row*K + kg];
      int sz = (row < M && kg+4 <= K) ? 16 : 0;
      if (!sz) src = A;
      unsigned dst = sA + (unsigned)(((s*128 + m)*36 + c4) << 2);
      asm volatile("cp.async.ca.shared.global [%0], [%1], 16, %2;\n"
                   :: "r"(dst), "l"(src), "r"(sz));
    }
    #pragma unroll
    for (int i = 0; i < 4; i++){
      int id = tid + i*256;
      int kk = id>>5, c4 = (id&31)*4;
      int kg = k0+kk;
      const float* src = &Bp[(size_t)kg*LPIX + col0 + c4];
      int sz = (kg < K) ? 16 : 0;
      if (!sz) src = Bp;
      unsigned dst = sB + (unsigned)(((s*32 + kk)*136 + c4) << 2);
      asm volatile("cp.async.cg.shared.global [%0], [%1], 16, %2;\n"
                   :: "r"(dst), "l"(src), "r"(sz));
    }
    asm volatile("cp.async.commit_group;\n");
  };

  float acc[4][4][4] = {};
  issue(0);
  for (int t = 0; t < nT; t++){
    if (t+1 < nT){ issue(t+1); asm volatile("cp.async.wait_group 1;\n" ::: "memory"); }
    else         {             asm volatile("cp.async.wait_group 0;\n" ::: "memory"); }
    __syncthreads();
    int s = t&1;
    #pragma unroll
    for (int ks = 0; ks < 4; ks++){
      int kb = ks*8;
      unsigned af[4][4], bfr[4][2];
      #pragma unroll
      for (int mt = 0; mt < 4; mt++){
        int r = wm*64 + mt*16 + (lane>>2);
        af[mt][0] = As[s][r  ][kb + (lane&3)];
        af[mt][1] = As[s][r+8][kb + (lane&3)];
        af[mt][2] = As[s][r  ][kb + 4 + (lane&3)];
        af[mt][3] = As[s][r+8][kb + 4 + (lane&3)];
      }
      #pragma unroll
      for (int nt = 0; nt < 4; nt++){
        int n = wn*32 + nt*8 + (lane>>2);
        bfr[nt][0] = f2tf(Bs[s][kb + (lane&3)][n]);
        bfr[nt][1] = f2tf(Bs[s][kb + 4 + (lane&3)][n]);
      }
      #pragma unroll
      for (int mt = 0; mt < 4; mt++)
        #pragma unroll
        for (int nt = 0; nt < 4; nt++)
          mma8(acc[mt][nt], af[mt], bfr[nt]);
    }
    __syncthreads();
  }
  size_t cb = (size_t)b*M*LPIX;
  #pragma unroll
  for (int mt = 0; mt < 4; mt++){
    int r = row0 + wm*64 + mt*16 + (lane>>2);
    #pragma unroll
    for (int nt = 0; nt < 4; nt++){
      int col = col0 + wn*32 + nt*8 + 2*(lane&3);
      float c0 = acc[mt][nt][0], c1 = acc[mt][nt][1];
      float c2 = acc[mt][nt][2], c3 = acc[mt][nt][3];
      if (EPI == 0){
        int g0 = b*LPIX + col;
        float r0v = colR[g0],  r1v = colR[g0+1];
        float m0v = colMR[g0], m1v = colMR[g0+1];
        if (r < M)
          st2<TC>(C, cb + (size_t)r*LPIX + col,
                  r0v*c0 - m0v*rowS[r] + rowC[r],
                  r1v*c1 - m1v*rowS[r] + rowC[r]);
        if (r+8 < M)
          st2<TC>(C, cb + (size_t)(r+8)*LPIX + col,
                  r0v*c2 - m0v*rowS[r+8] + rowC[r+8],
                  r1v*c3 - m1v*rowS[r+8] + rowC[r+8]);
      } else {
        if (r < M){
          size_t ci = cb + (size_t)r*LPIX + col;
          float2 rr = *(const float2*)&res[ci];
          st2<TC>(C, ci, c0 + rowC[r] + rr.x, c1 + rowC[r] + rr.y);
        }
        if (r+8 < M){
          size_t ci = cb + (size_t)(r+8)*LPIX + col;
          float2 rr = *(const float2*)&res[ci];
          st2<TC>(C, ci, c2 + rowC[r+8] + rr.x, c3 + rowC[r+8] + rr.y);
        }
      }
    }
  }
}

// ======== TF32 GEMM with bf16 B (ffn_out), cp.async 2-stage, res epilogue ========
// A must be PRE-ROUNDED to tf32. B stored raw bf16 in smem, expanded at frag build.
#define GEMM_BF_SMEM (2*64*36*4 + 2*32*136*2)
__global__ __launch_bounds__(256)
void gemm_bf(const float* __restrict__ A, const bf16* __restrict__ Bm,
             float* __restrict__ C, int M, int K,
             const float* __restrict__ res){
  extern __shared__ float smem[];
  unsigned (*As)[64][36] = (unsigned(*)[64][36])smem;
  uint16_t (*Bs)[32][136] = (uint16_t(*)[32][136])(smem + 2*64*36);
  int tid = threadIdx.x;
  int b = blockIdx.z;
  int row0 = blockIdx.x*64, col0 = blockIdx.y*128;
  const bf16* Bp = Bm + (size_t)b*K*LPIX;
  int lane = tid&31, warp = tid>>5;
  int wm = warp>>2, wn = warp&3;
  int nT = (K+31)>>5;
  unsigned sA = (unsigned)__cvta_generic_to_shared(&As[0][0][0]);
  unsigned sB = (unsigned)__cvta_generic_to_shared(&Bs[0][0][0]);

  auto issue = [&](int t){
    int s = t&1, k0 = t*32;
    #pragma unroll
    for (int i = 0; i < 2; i++){
      int id = tid + i*256;
      int m = id>>3, c4 = (id&7)*4;
      int row = row0+m, kg = k0+c4;
      const float* src = &A[(size_t)row*K + kg];
      int sz = (row < M && kg+4 <= K) ? 16 : 0;
      if (!sz) src = A;
      unsigned dst = sA + (unsigned)(((s*64 + m)*36 + c4) << 2);
      asm volatile("cp.async.ca.shared.global [%0], [%1], 16, %2;\n"
                   :: "r"(dst), "l"(src), "r"(sz));
    }
    #pragma unroll
    for (int i = 0; i < 2; i++){
      int id = tid + i*256;
      int kk = id>>4, c8 = (id&15)*8;       // 8 bf16 = 16 bytes
      int kg = k0+kk;
      const bf16* src = &Bp[(size_t)kg*LPIX + col0 + c8];
      int sz = (kg < K) ? 16 : 0;
      if (!sz) src = Bp;
      unsigned dst = sB + (unsigned)(((s*32 + kk)*136 + c8) << 1);
      asm volatile("cp.async.cg.shared.global [%0], [%1], 16, %2;\n"
                   :: "r"(dst), "l"(src), "r"(sz));
    }
    asm volatile("cp.async.commit_group;\n");
  };

  float acc[2][4][4] = {};
  issue(0);
  for (int t = 0; t < nT; t++){
    if (t+1 < nT){ issue(t+1); asm volatile("cp.async.wait_group 1;\n" ::: "memory"); }
    else         {             asm volatile("cp.async.wait_group 0;\n" ::: "memory"); }
    __syncthreads();
    int s = t&1;
    #pragma unroll
    for (int ks = 0; ks < 4; ks++){
      int kb = ks*8;
      unsigned af[2][4], bfr[4][2];
      #pragma unroll
      for (int mt = 0; mt < 2; mt++){
        int r = wm*32 + mt*16 + (lane>>2);
        af[mt][0] = As[s][r  ][kb + (lane&3)];
        af[mt][1] = As[s][r+8][kb + (lane&3)];
        af[mt][2] = As[s][r  ][kb + 4 + (lane&3)];
        af[mt][3] = As[s][r+8][kb + 4 + (lane&3)];
      }
      #pragma unroll
      for (int nt = 0; nt < 4; nt++){
        int n = wn*32 + nt*8 + (lane>>2);
        bfr[nt][0] = ((unsigned)Bs[s][kb + (lane&3)][n]) << 16;
        bfr[nt][1] = ((unsigned)Bs[s][kb + 4 + (lane&3)][n]) << 16;
      }
      #pragma unroll
      for (int mt = 0; mt < 2; mt++)
        #pragma unroll
        for (int nt = 0; nt < 4; nt++)
          mma8(acc[mt][nt], af[mt], bfr[nt]);
    }
    __syncthreads();
  }
  size_t cb = (size_t)b*M*LPIX;
  #pragma unroll
  for (int mt = 0; mt < 2; mt++){
    int r = row0 + wm*32 + mt*16 + (lane>>2);
    #pragma unroll
    for (int nt = 0; nt < 4; nt++){
      int col = col0 + wn*32 + nt*8 + 2*(lane&3);
      if (r < M){
        size_t ci = cb + (size_t)r*LPIX + col;
        float2 rr = *(const float2*)&res[ci];
        st2<float>(C, ci, acc[mt][nt][0] + rr.x, acc[mt][nt][1] + rr.y);
      }
      if (r+8 < M){
        size_t ci = cb + (size_t)(r+8)*LPIX + col;
        float2 rr = *(const float2*)&res[ci];
        st2<float>(C, ci, acc[mt][nt][2] + rr.x, acc[mt][nt][3] + rr.y);
      }
    }
  }
}

// ---------------- RoPE helpers (head_dim = 8) ----------------
__device__ __forceinline__ void rope_sc8(int l, float* sn, float* cs){
  int hh = l >> 7, ww = l & 127;
  sincosf((float)hh,          &sn[0], &cs[0]);
  sincosf((float)hh * 1e-4f,  &sn[1], &cs[1]);
  sincosf((float)ww,          &sn[2], &cs[2]);
  sincosf((float)ww * 1e-4f,  &sn[3], &cs[3]);
}
__device__ __forceinline__ void theta_shift8(const float* x, const float* sn,
                                             const float* cs, float* y){
  #pragma unroll
  for (int p = 0; p < 4; p++){
    y[2*p]   = x[2*p]  *cs[p] - x[2*p+1]*sn[p];
    y[2*p+1] = x[2*p+1]*cs[p] + x[2*p]  *sn[p];
  }
}

// ---------------- attention reductions: split-K partials ----------------
__global__ __launch_bounds__(256)
void attn_reduce_k(){
  int nh = blockIdx.x, b = blockIdx.y, sp = blockIdx.z;
  const float* kp = g_qkvo + ((size_t)b*QM +   CDIM + nh*8)*LPIX;
  const float* vp = g_qkvo + ((size_t)b*QM + 2*CDIM + nh*8)*LPIX;
  float mk[8] = {}, mv[8] = {}, kv[64] = {};
  int l0 = sp*(LPIX/NSPLIT), l1 = l0 + (LPIX/NSPLIT);
  for (int l = l0 + threadIdx.x; l < l1; l += 256){
    float kk[8], vv[8], ks[8], sn[4], cs[4];
    #pragma unroll
    for (int d = 0; d < 8; d++){
      float kl = kp[(size_t)d*LPIX + l];
      kk[d] = kl > 0.f ? kl + 1.f : expf(kl);   // elu(k)+1
      vv[d] = vp[(size_t)d*LPIX + l];
      mk[d] += kk[d];
      mv[d] += vv[d];
    }
    rope_sc8(l, sn, cs);
    theta_shift8(kk, sn, cs, ks);
    #pragma unroll
    for (int d = 0; d < 8; d++)
      #pragma unroll
      for (int e = 0; e < 8; e++)
        kv[d*8+e] = fmaf(ks[d], vv[e], kv[d*8+e]);
  }
  __shared__ float red[8][80];
  int warp = threadIdx.x >> 5, lane = threadIdx.x & 31;
  #pragma unroll
  for (int i = 0; i < 8; i++){
    #pragma unroll
    for (int off = 16; off > 0; off >>= 1){
      mk[i] += __shfl_down_sync(0xffffffffu, mk[i], off);
      mv[i] += __shfl_down_sync(0xffffffffu, mv[i], off);
    }
  }
  #pragma unroll
  for (int i = 0; i < 64; i++)
    #pragma unroll
    for (int off = 16; off > 0; off >>= 1)
      kv[i] += __shfl_down_sync(0xffffffffu, kv[i], off);
  if (lane == 0){
    #pragma unroll
    for (int i = 0; i < 8; i++){ red[warp][i] = mk[i]; red[warp][8+i] = mv[i]; }
    #pragma unroll
    for (int i = 0; i < 64; i++) red[warp][16+i] = kv[i];
  }
  __syncthreads();
  int t = threadIdx.x;
  if (t < 80){
    float s = 0.f;
    #pragma unroll
    for (int w = 0; w < 8; w++) s += red[w][t];
    g_part[((b*NH + nh)*NSPLIT + sp)*80 + t] = s;
  }
}

// ---------------- finalize: sum split partials (deterministic) ----------------
__global__ void attn_fin_k(){
  int o = blockIdx.x;            // b*NH + nh
  int t = threadIdx.x;           // 0..79
  float s = 0.f;
  #pragma unroll
  for (int sp = 0; sp < NSPLIT; sp++) s += g_part[(o*NSPLIT + sp)*80 + t];
  if (t < 8)        g_mk[o*8 + t]       = s * (1.f/LPIX);
  else if (t < 16)  g_mv[o*8 + t - 8]   = s * (1.f/LPIX);
  else              g_kv[o*64 + t - 16] = s * (ATT_SCALE/LPIX);
}

// ---------------- attention apply + lepe add + gate by o ----------------
__global__ __launch_bounds__(256)
void attn_apply_k(){
  int b = blockIdx.z, nh = blockIdx.y;
  int tid = threadIdx.x;
  int l = blockIdx.x*256 + tid;
  __shared__ float skv[64], smk[8], smv[8];
  int o = b*NH + nh;
  if (tid < 64)       skv[tid]      = g_kv[o*64 + tid];
  else if (tid < 72)  smk[tid-64]   = g_mk[o*8 + tid-64];
  else if (tid < 80)  smv[tid-72]   = g_mv[o*8 + tid-72];
  __syncthreads();
  const float* qp = g_qkvo + ((size_t)b*QM +          nh*8)*LPIX + l;
  const float* op = g_qkvo + ((size_t)b*QM + 3*CDIM + nh*8)*LPIX + l;
  const float* lp = g_lepe + ((size_t)b*CDIM + nh*8)*LPIX + l;
  float*       pp = g_po   + ((size_t)b*CDIM + nh*8)*LPIX + l;
  float qq[8], qs[8], sn[4], cs[4];
  #pragma unroll
  for (int d = 0; d < 8; d++){
    float qv = qp[(size_t)d*LPIX];
    qq[d] = qv > 0.f ? qv + 1.f : expf(qv);     // elu(q)+1
  }
  float z = 0.f;
  #pragma unroll
  for (int d = 0; d < 8; d++) z = fmaf(qq[d], smk[d], z);
  z *= ATT_SCALE;
  rope_sc8(l, sn, cs);
  theta_shift8(qq, sn, cs, qs);
  float f = 1.f + 1.f/(z + 1e-6f);
  #pragma unroll
  for (int e = 0; e < 8; e++){
    float r = 0.f;
    #pragma unroll
    for (int d = 0; d < 8; d++) r = fmaf(qs[d], skv[d*8 + e], r);
    float rv = r*f - z*smv[e];
    pp[(size_t)e*LPIX] = (rv + lp[(size_t)e*LPIX]) * op[(size_t)e*LPIX];
  }
}

// ---------------- lepe: 5x5 depthwise conv on v-channels of qkvo ----------------
__global__ __launch_bounds__(256)
void lepe_k(const float* __restrict__ w, const float* __restrict__ bias){
  int z = blockIdx.z;
  int b = z >> 7, c = z & 127;
  const float* src = g_qkvo + ((size_t)b*QM + 2*CDIM + c)*LPIX;
  __shared__ float t[36][36];
  __shared__ float wk[25];
  int tid = threadIdx.x;
  if (tid < 25) wk[tid] = w[c*25 + tid];
  int y0 = blockIdx.y*32 - 2, x0 = blockIdx.x*32 - 2;
  for (int i = tid; i < 36*36; i += 256){
    int yy = i/36, xx = i - yy*36;
    int gy = y0 + yy, gx = x0 + xx;
    t[yy][xx] = ((unsigned)gy < 128u && (unsigned)gx < 128u) ? src[gy*HW + gx] : 0.f;
  }
  __syncthreads();
  float bb = bias[c];
  int tx = tid & 31, tyb = tid >> 5;
  float* dst = g_lepe + ((size_t)b*CDIM + c)*LPIX;
  #pragma unroll
  for (int r = 0; r < 4; r++){
    int ty = tyb + r*8;
    float acc = bb;
    #pragma unroll
    for (int dy = 0; dy < 5; dy++)
      #pragma unroll
      for (int dx = 0; dx < 5; dx++)
        acc = fmaf(t[ty+dy][tx+dx], wk[dy*5+dx], acc);
    dst[(blockIdx.y*32 + ty)*HW + blockIdx.x*32 + tx] = acc;
  }
}

// ---------------- FFN: 3x3 depthwise on both halves + gelu(x1)*x2 ----------------
__global__ __launch_bounds__(256)
void ffn_dw_k(const float* __restrict__ w){
  int z = blockIdx.z;
  int b = z / HIDN, j = z - b*HIDN;
  const float* s1 = g_p + ((size_t)b*HID2N + j)*LPIX;
  const float* s2 = g_p + ((size_t)b*HID2N + HIDN + j)*LPIX;
  __shared__ float t1[34][34], t2[34][34];
  __shared__ float w1[9], w2[9];
  int tid = threadIdx.x;
  if (tid < 9)        w1[tid]   = w[j*9 + tid];
  else if (tid < 18)  w2[tid-9] = w[(HIDN + j)*9 + tid - 9];
  int y0 = blockIdx.y*32 - 1, x0 = blockIdx.x*32 - 1;
  for (int i = tid; i < 34*34; i += 256){
    int yy = i/34, xx = i - yy*34;
    int gy = y0 + yy, gx = x0 + xx;
    bool in = ((unsigned)gy < 128u && (unsigned)gx < 128u);
    t1[yy][xx] = in ? s1[gy*HW + gx] : 0.f;
    t2[yy][xx] = in ? s2[gy*HW + gx] : 0.f;
  }
  __syncthreads();
  int tx = tid & 31, tyb = tid >> 5;
  bf16* dst = g_gt + ((size_t)b*HIDN + j)*LPIX;
  #pragma unroll
  for (int r = 0; r < 4; r++){
    int ty = tyb + r*8;
    float a1 = 0.f, a2 = 0.f;
    #pragma unroll
    for (int dy = 0; dy < 3; dy++)
      #pragma unroll
      for (int dx = 0; dx < 3; dx++){
        a1 = fmaf(t1[ty+dy][tx+dx], w1[dy*3+dx], a1);
        a2 = fmaf(t2[ty+dy][tx+dx], w2[dy*3+dx], a2);
      }
    float ge = a1 * normcdff(a1);                 // exact gelu
    dst[(blockIdx.y*32 + ty)*HW + blockIdx.x*32 + tx] = __float2bfloat16(ge * a2);
  }
}

// ---------------- launch ----------------
extern "C" void kernel_launch(void* const* d_in, const int* in_sizes, int n_in,
                              void* d_out, int out_size){
  (void)in_sizes; (void)n_in; (void)out_size;
  const float* x        = (const float*)d_in[0];
  const float* ln1_w    = (const float*)d_in[1];
  const float* ln1_b    = (const float*)d_in[2];
  const float* qkvo_w   = (const float*)d_in[3];
  const float* qkvo_b   = (const float*)d_in[4];
  const float* lepe_w   = (const float*)d_in[5];
  const float* lepe_b   = (const float*)d_in[6];
  const float* proj_w   = (const float*)d_in[7];
  const float* proj_b   = (const float*)d_in[8];
  const float* ln2_w    = (const float*)d_in[9];
  const float* ln2_b    = (const float*)d_in[10];
  const float* ffn_in_w = (const float*)d_in[11];
  const float* ffn_dw_w = (const float*)d_in[12];
  const float* ffn_out_w= (const float*)d_in[13];
  float* out = (float*)d_out;

  void *p_rstd1, *p_mur1, *p_rstd2, *p_mur2, *p_qkvo, *p_po, *p_xb, *p_p, *p_gt;
  void *p_w1p, *p_rs1, *p_c1, *p_w2p, *p_rs2, *p_c2, *p_wproj, *p_wffo;
  cudaGetSymbolAddress(&p_rstd1, g_rstd1);
  cudaGetSymbolAddress(&p_mur1,  g_mur1);
  cudaGetSymbolAddress(&p_rstd2, g_rstd2);
  cudaGetSymbolAddress(&p_mur2,  g_mur2);
  cudaGetSymbolAddress(&p_qkvo,  g_qkvo);
  cudaGetSymbolAddress(&p_po,    g_po);
  cudaGetSymbolAddress(&p_xb,    g_xb);
  cudaGetSymbolAddress(&p_p,     g_p);
  cudaGetSymbolAddress(&p_gt,    g_gt);
  cudaGetSymbolAddress(&p_w1p,   g_w1p);
  cudaGetSymbolAddress(&p_rs1,   g_rs1);
  cudaGetSymbolAddress(&p_c1,    g_c1);
  cudaGetSymbolAddress(&p_w2p,   g_w2p);
  cudaGetSymbolAddress(&p_rs2,   g_rs2);
  cudaGetSymbolAddress(&p_c2,    g_c2);
  cudaGetSymbolAddress(&p_wproj, g_wproj);
  cudaGetSymbolAddress(&p_wffo,  g_wffo);

  static int smem_set = 0;
  if (!smem_set){
    cudaFuncSetAttribute(gemm128<0,float>, cudaFuncAttributeMaxDynamicSharedMemorySize, GEMM_SMEM2);
    cudaFuncSetAttribute(gemm128<1,float>, cudaFuncAttributeMaxDynamicSharedMemorySize, GEMM_SMEM2);
    cudaFuncSetAttribute(gemm_bf,          cudaFuncAttributeMaxDynamicSharedMemorySize, GEMM_BF_SMEM);
    smem_set = 1;
  }

  // fold LN affine into conv weights + pre-round to tf32 (tiny)
  fold_k<<<QM,    CDIM>>>(qkvo_w,   ln1_w, ln1_b, qkvo_b, (float*)p_w1p, (float*)p_rs1, (float*)p_c1, 1);
  fold_k<<<HID2N, CDIM>>>(ffn_in_w, ln2_w, ln2_b, nullptr,(float*)p_w2p, (float*)p_rs2, (float*)p_c2, 0);
  roundw_k<<<(CDIM*CDIM+255)/256, 256>>>(proj_w,    (float*)p_wproj, CDIM*CDIM);
  roundw_k<<<(CDIM*HIDN+255)/256, 256>>>(ffn_out_w, (float*)p_wffo,  CDIM*HIDN);

  // LN1 stats
  ln_stats_k<<<NPIX/256, 256>>>(x, (float*)p_rstd1, (float*)p_mur1);

  // qkvo = conv1x1(LN1(x)) + b   (LN folded, pipelined tf32, 128x128 tile)
  gemm128<0,float><<<dim3(4, 128, BATCH), 256, GEMM_SMEM2>>>(
      (float*)p_w1p, x, (float*)p_qkvo, QM, CDIM,
      (float*)p_rs1, (float*)p_c1, (float*)p_rstd1, (float*)p_mur1, nullptr);

  // lepe = dwconv5x5(v) + b
  lepe_k<<<dim3(4, 4, BATCH*CDIM), 256>>>(lepe_w, lepe_b);

  // per-(b,head) reductions: meank, meanv, kv  (split-K, deterministic)
  attn_reduce_k<<<dim3(NH, BATCH, NSPLIT), 256>>>();
  attn_fin_k<<<BATCH*NH, 80>>>();

  // res = q@kv * (1+1/z) - z*meanv ; po = (res + lepe) * o
  attn_apply_k<<<dim3(LPIX/256, NH, BATCH), 256>>>();

  // xb = x + conv1x1(po, proj_w) + proj_b
  gemm128<1,float><<<dim3(1, 128, BATCH), 256, GEMM_SMEM2>>>(
      (float*)p_wproj, (float*)p_po, (float*)p_xb, CDIM, CDIM,
      nullptr, proj_b, nullptr, nullptr, x);

  // LN2 stats
  ln_stats_k<<<NPIX/256, 256>>>((float*)p_xb, (float*)p_rstd2, (float*)p_mur2);

  // p = conv1x1(LN2(xb), ffn_in_w)   (LN folded, fp32 out for precision)
  gemm128<0,float><<<dim3(6, 128, BATCH), 256, GEMM_SMEM2>>>(
      (float*)p_w2p, (float*)p_xb, (float*)p_p, HID2N, CDIM,
      (float*)p_rs2, (float*)p_c2, (float*)p_rstd2, (float*)p_mur2, nullptr);

  // g = gelu(dw3(p[:340])) * dw3(p[340:])  (fp32 in, bf16 out)
  ffn_dw_k<<<dim3(4, 4, BATCH*HIDN), 256>>>(ffn_dw_w);

  // out = xb + conv1x1(g, ffn_out_w)  (bf16 B, pre-rounded A, pipelined)
  gemm_bf<<<dim3(2, 128, BATCH), 256, GEMM_BF_SMEM>>>(
      (float*)p_wffo, (bf16*)p_gt, out, CDIM, HIDN, (float*)p_xb);
}